// round 7
// baseline (speedup 1.0000x reference)
#include <cuda_runtime.h>

#define EPS 1e-5f

typedef unsigned long long u64;
typedef unsigned int u32;

__device__ __forceinline__ u32 to_tf32(float v) {
    u32 r; asm("cvt.rna.tf32.f32 %0, %1;" : "=r"(r) : "f"(v)); return r;
}
__device__ __forceinline__ void mma_tf32(float* d, const u32* a, const u32* b) {
    asm volatile(
        "mma.sync.aligned.m16n8k8.row.col.f32.tf32.tf32.f32 "
        "{%0,%1,%2,%3}, {%4,%5,%6,%7}, {%8,%9}, {%0,%1,%2,%3};\n"
        : "+f"(d[0]), "+f"(d[1]), "+f"(d[2]), "+f"(d[3])
        : "r"(a[0]), "r"(a[1]), "r"(a[2]), "r"(a[3]), "r"(b[0]), "r"(b[1]));
}

// Scratch: qkv[n=8][o=256][h=128][w=128] fp32 = 128 MB
__device__ float g_qkv[33554432];
// W transposed+split: [c=128][o=256] hi / lo
__device__ float g_wt_hi[32768];
__device__ float g_wt_lo[32768];

// ---------------- Kernel 0: transpose + tf32-split W ----------------
__global__ void wt_kernel(const float* __restrict__ w) {
    int idx = blockIdx.x * 256 + threadIdx.x;   // 0..32767
    int o = idx >> 7, c = idx & 127;
    float v = w[idx];
    float hf = __uint_as_float(to_tf32(v));
    g_wt_hi[c * 256 + o] = hf;
    g_wt_lo[c * 256 + o] = __uint_as_float(to_tf32(v - hf));
}

// ---------------- Kernel 1: QKV GEMM via tf32 mma.sync + BN ----------------
// Block: 64o x 128p, 128 threads = 4 warps (2x2), warp tile 32o x 64p.
// Compensated tf32 (Ah*Bh + Ah*Bl + Al*Bh).
#define QSM (26752 * 4)

__global__ __launch_bounds__(128) void qkv_kernel(
    const float* __restrict__ x,
    const float* __restrict__ qg, const float* __restrict__ qb,
    const float* __restrict__ qm, const float* __restrict__ qv) {
    extern __shared__ float qs[];
    float* xs_hi = qs;
    float* xs_lo = qs + 8704;
    float* ws_hi = qs + 17408;
    float* ws_lo = qs + 22016;
    float* sbn   = qs + 26624;
    float* tbn   = qs + 26688;

    int tid = threadIdx.x;
    int lane = tid & 31, wid = tid >> 5;
    int wm = wid >> 1, wn = wid & 1;
    int pt = blockIdx.x, ot = blockIdx.y, nb = blockIdx.z;
    const float* xp = x + (size_t)nb * (128 * 16384) + pt * 128;

    if (tid < 64) {
        int o = ot * 64 + tid;
        float s = qg[o] * rsqrtf(qv[o] + EPS);
        sbn[tid] = s;
        tbn[tid] = qb[o] - qm[o] * s;
    }

    float d[2][8][4];
#pragma unroll
    for (int m = 0; m < 2; m++)
#pragma unroll
        for (int n = 0; n < 8; n++)
#pragma unroll
            for (int r = 0; r < 4; r++) d[m][n][r] = 0.f;

    int row = lane >> 2, kq = lane & 3;

    for (int cc = 0; cc < 2; cc++) {
#pragma unroll
        for (int k = 0; k < 16; k++) {
            int f = tid + k * 128;
            int c = f >> 5, p4 = (f & 31) << 2;
            float4 v = *(const float4*)(xp + (size_t)(cc * 64 + c) * 16384 + p4);
            float4 h, l;
            h.x = __uint_as_float(to_tf32(v.x)); l.x = __uint_as_float(to_tf32(v.x - h.x));
            h.y = __uint_as_float(to_tf32(v.y)); l.y = __uint_as_float(to_tf32(v.y - h.y));
            h.z = __uint_as_float(to_tf32(v.z)); l.z = __uint_as_float(to_tf32(v.z - h.z));
            h.w = __uint_as_float(to_tf32(v.w)); l.w = __uint_as_float(to_tf32(v.w - h.w));
            *(float4*)&xs_hi[c * 136 + p4] = h;
            *(float4*)&xs_lo[c * 136 + p4] = l;
        }
#pragma unroll
        for (int k = 0; k < 8; k++) {
            int f = tid + k * 128;
            int c = f >> 4, o4 = (f & 15) << 2;
            *(float4*)&ws_hi[c * 72 + o4] =
                *(const float4*)(g_wt_hi + (cc * 64 + c) * 256 + ot * 64 + o4);
            *(float4*)&ws_lo[c * 72 + o4] =
                *(const float4*)(g_wt_lo + (cc * 64 + c) * 256 + ot * 64 + o4);
        }
        __syncthreads();

#pragma unroll
        for (int kc = 0; kc < 8; kc++) {
            int k0 = kc * 8 + kq;
            u32 ah[2][4], al[2][4];
#pragma unroll
            for (int m = 0; m < 2; m++) {
                int wo = wm * 32 + m * 16;
                ah[m][0] = __float_as_uint(ws_hi[k0 * 72 + wo + row]);
                ah[m][1] = __float_as_uint(ws_hi[k0 * 72 + wo + row + 8]);
                ah[m][2] = __float_as_uint(ws_hi[(k0 + 4) * 72 + wo + row]);
                ah[m][3] = __float_as_uint(ws_hi[(k0 + 4) * 72 + wo + row + 8]);
                al[m][0] = __float_as_uint(ws_lo[k0 * 72 + wo + row]);
                al[m][1] = __float_as_uint(ws_lo[k0 * 72 + wo + row + 8]);
                al[m][2] = __float_as_uint(ws_lo[(k0 + 4) * 72 + wo + row]);
                al[m][3] = __float_as_uint(ws_lo[(k0 + 4) * 72 + wo + row + 8]);
            }
#pragma unroll
            for (int n = 0; n < 8; n++) {
                int pc = wn * 64 + n * 8 + row;
                u32 bh[2], bl[2];
                bh[0] = __float_as_uint(xs_hi[k0 * 136 + pc]);
                bh[1] = __float_as_uint(xs_hi[(k0 + 4) * 136 + pc]);
                bl[0] = __float_as_uint(xs_lo[k0 * 136 + pc]);
                bl[1] = __float_as_uint(xs_lo[(k0 + 4) * 136 + pc]);
#pragma unroll
                for (int m = 0; m < 2; m++) {
                    mma_tf32(d[m][n], ah[m], bh);
                    mma_tf32(d[m][n], ah[m], bl);
                    mma_tf32(d[m][n], al[m], bh);
                }
            }
        }
        __syncthreads();
    }
#pragma unroll
    for (int m = 0; m < 2; m++) {
        int lo0 = wm * 32 + m * 16 + row;
        float s0 = sbn[lo0],     t0 = tbn[lo0];
        float s1 = sbn[lo0 + 8], t1 = tbn[lo0 + 8];
        int o0 = ot * 64 + lo0;
#pragma unroll
        for (int n = 0; n < 8; n++) {
            int p = pt * 128 + wn * 64 + n * 8 + kq * 2;
            float2 r0, r1;
            r0.x = d[m][n][0] * s0 + t0; r0.y = d[m][n][1] * s0 + t0;
            r1.x = d[m][n][2] * s1 + t1; r1.y = d[m][n][3] * s1 + t1;
            *(float2*)(g_qkv + (size_t)(nb * 256 + o0) * 16384 + p) = r0;
            *(float2*)(g_qkv + (size_t)(nb * 256 + o0 + 8) * 16384 + p) = r1;
        }
    }
}

// ---------------- Kernel 2: MMA attention per (n, g, 4-wide w tile) ----------------
// 256 threads = 8 warps; warp wid owns i-rows [wid*16, wid*16+16).
// GEMM1: S = Q^T K (M=128 i, N=128 j, K=8 c), compensated tf32.
// softmax in fragments; P -> smem; GEMM2: O^T = V P^T (M=16 c, N=16 i/warp, K=128 j).
// smem (floats):
//   stage [4][32][128] : 0      (16384)
//   qk_hi [16][136]    : 16384  (2176)
//   qk_lo [16][136]    : 18560  (2176)
//   v_hi  [16][132]    : 20736  (2112)
//   v_lo  [16][132]    : 22848  (2112)
//   Psm   [128][132]   : 24960  (16896)
//   sinv  [128]        : 41856
//   ostage[16][128][4] : 41984  (8192)
//   osc[16]            : 50176
//   osh[16]            : 50192
#define SMEM2 (50208 * 4)

__global__ __launch_bounds__(256) void attn_kernel(
    const float* __restrict__ simg, const float* __restrict__ simv,
    const float* __restrict__ og, const float* __restrict__ obt,
    const float* __restrict__ om, const float* __restrict__ ov,
    float* __restrict__ out) {
    extern __shared__ float sm[];
    float* stage  = sm;
    float* qk_hi  = sm + 16384;
    float* qk_lo  = sm + 18560;
    float* v_hi   = sm + 20736;
    float* v_lo   = sm + 22848;
    float* Psm    = sm + 24960;
    float* sinv   = sm + 41856;
    float* ostage = sm + 41984;
    float* osc    = sm + 50176;
    float* osh    = sm + 50192;

    int tid = threadIdx.x;
    int lane = tid & 31, wid = tid >> 5;
    int row = lane >> 2, kq = lane & 3;
    int i0 = wid * 16;
    int w0 = blockIdx.x * 4;
    int g  = blockIdx.y;
    int n  = blockIdx.z;

    // stage 32ch x 128h x 4w (coalesced float4 over w)
    const float* src = g_qkv + (size_t)(n * 256 + g * 32) * 16384 + w0;
#pragma unroll
    for (int k = 0; k < 16; k++) {
        int f = tid + k * 256;
        int h = f & 127, ch = f >> 7;
        float4 v4 = *(const float4*)(src + (size_t)ch * 16384 + h * 128);
        stage[(0 * 32 + ch) * 128 + h] = v4.x;
        stage[(1 * 32 + ch) * 128 + h] = v4.y;
        stage[(2 * 32 + ch) * 128 + h] = v4.z;
        stage[(3 * 32 + ch) * 128 + h] = v4.w;
    }
    if (tid < 16) {
        int co = g * 16 + tid;
        float s = og[co] * rsqrtf(ov[co] + EPS);
        osc[tid] = s;
        osh[tid] = obt[co] - om[co] * s;
    }
    // sim BN shift cancels in softmax; positive scale folded into Q.
    float simscale = simg[g] * rsqrtf(simv[g] + EPS);
    __syncthreads();

#pragma unroll 1
    for (int ww = 0; ww < 4; ww++) {
        // ---- tf32 split pass (Q scaled by simscale) ----
#pragma unroll
        for (int k = 0; k < 16; k++) {
            int f = tid + k * 256;
            int h = f & 127, ch = f >> 7;
            float v = stage[(ww * 32 + ch) * 128 + h];
            if (ch < 8) v *= simscale;
            float hi = __uint_as_float(to_tf32(v));
            float lo = __uint_as_float(to_tf32(v - hi));
            if (ch < 16) { qk_hi[ch * 136 + h] = hi; qk_lo[ch * 136 + h] = lo; }
            else { v_hi[(ch - 16) * 132 + h] = hi; v_lo[(ch - 16) * 132 + h] = lo; }
        }
        __syncthreads();

        // ---- GEMM1: S rows [i0, i0+16) ----
        u32 ah[4], al[4];
        ah[0] = __float_as_uint(qk_hi[kq * 136 + i0 + row]);
        ah[1] = __float_as_uint(qk_hi[kq * 136 + i0 + row + 8]);
        ah[2] = __float_as_uint(qk_hi[(kq + 4) * 136 + i0 + row]);
        ah[3] = __float_as_uint(qk_hi[(kq + 4) * 136 + i0 + row + 8]);
        al[0] = __float_as_uint(qk_lo[kq * 136 + i0 + row]);
        al[1] = __float_as_uint(qk_lo[kq * 136 + i0 + row + 8]);
        al[2] = __float_as_uint(qk_lo[(kq + 4) * 136 + i0 + row]);
        al[3] = __float_as_uint(qk_lo[(kq + 4) * 136 + i0 + row + 8]);

        float sreg[16][4];
#pragma unroll
        for (int t = 0; t < 16; t++) {
            sreg[t][0] = 0.f; sreg[t][1] = 0.f; sreg[t][2] = 0.f; sreg[t][3] = 0.f;
            u32 bh[2], bl[2];
            bh[0] = __float_as_uint(qk_hi[(8 + kq) * 136 + t * 8 + row]);
            bh[1] = __float_as_uint(qk_hi[(12 + kq) * 136 + t * 8 + row]);
            bl[0] = __float_as_uint(qk_lo[(8 + kq) * 136 + t * 8 + row]);
            bl[1] = __float_as_uint(qk_lo[(12 + kq) * 136 + t * 8 + row]);
            mma_tf32(sreg[t], ah, bh);
            mma_tf32(sreg[t], ah, bl);
            mma_tf32(sreg[t], al, bh);
        }

        // ---- softmax (rows i0+row, i0+row+8) ----
        float m0 = -1e30f, m1 = -1e30f;
#pragma unroll
        for (int t = 0; t < 16; t++) {
            m0 = fmaxf(m0, fmaxf(sreg[t][0], sreg[t][1]));
            m1 = fmaxf(m1, fmaxf(sreg[t][2], sreg[t][3]));
        }
        m0 = fmaxf(m0, __shfl_xor_sync(0xffffffffu, m0, 1));
        m0 = fmaxf(m0, __shfl_xor_sync(0xffffffffu, m0, 2));
        m1 = fmaxf(m1, __shfl_xor_sync(0xffffffffu, m1, 1));
        m1 = fmaxf(m1, __shfl_xor_sync(0xffffffffu, m1, 2));
        float s0 = 0.f, s1 = 0.f;
#pragma unroll
        for (int t = 0; t < 16; t++) {
            float e0 = __expf(sreg[t][0] - m0);
            float e1 = __expf(sreg[t][1] - m0);
            float e2 = __expf(sreg[t][2] - m1);
            float e3 = __expf(sreg[t][3] - m1);
            sreg[t][0] = e0; sreg[t][1] = e1; sreg[t][2] = e2; sreg[t][3] = e3;
            s0 += e0 + e1; s1 += e2 + e3;
        }
        s0 += __shfl_xor_sync(0xffffffffu, s0, 1);
        s0 += __shfl_xor_sync(0xffffffffu, s0, 2);
        s1 += __shfl_xor_sync(0xffffffffu, s1, 1);
        s1 += __shfl_xor_sync(0xffffffffu, s1, 2);
        if (kq == 0) {
            sinv[i0 + row] = 1.f / s0;
            sinv[i0 + row + 8] = 1.f / s1;
        }
        // P -> smem (float2 pairs, consecutive cols)
#pragma unroll
        for (int t = 0; t < 16; t++) {
            float2 p01; p01.x = sreg[t][0]; p01.y = sreg[t][1];
            float2 p23; p23.x = sreg[t][2]; p23.y = sreg[t][3];
            *(float2*)&Psm[(i0 + row) * 132 + t * 8 + 2 * kq] = p01;
            *(float2*)&Psm[(i0 + row + 8) * 132 + t * 8 + 2 * kq] = p23;
        }
        __syncthreads();

        // ---- GEMM2: O^T = V P^T, n-tile = this warp's 16 i rows ----
        float o[2][4];
#pragma unroll
        for (int nt = 0; nt < 2; nt++)
#pragma unroll
            for (int r = 0; r < 4; r++) o[nt][r] = 0.f;
#pragma unroll
        for (int ks = 0; ks < 16; ks++) {
            int j0 = ks * 8;
            u32 vh[4], vl[4];
            vh[0] = __float_as_uint(v_hi[row * 132 + j0 + kq]);
            vh[1] = __float_as_uint(v_hi[(row + 8) * 132 + j0 + kq]);
            vh[2] = __float_as_uint(v_hi[row * 132 + j0 + kq + 4]);
            vh[3] = __float_as_uint(v_hi[(row + 8) * 132 + j0 + kq + 4]);
            vl[0] = __float_as_uint(v_lo[row * 132 + j0 + kq]);
            vl[1] = __float_as_uint(v_lo[(row + 8) * 132 + j0 + kq]);
            vl[2] = __float_as_uint(v_lo[row * 132 + j0 + kq + 4]);
            vl[3] = __float_as_uint(v_lo[(row + 8) * 132 + j0 + kq + 4]);
#pragma unroll
            for (int nt = 0; nt < 2; nt++) {
                float p0 = Psm[(i0 + nt * 8 + row) * 132 + j0 + kq];
                float p1 = Psm[(i0 + nt * 8 + row) * 132 + j0 + kq + 4];
                u32 ph[2], pl[2];
                ph[0] = to_tf32(p0);
                pl[0] = to_tf32(p0 - __uint_as_float(ph[0]));
                ph[1] = to_tf32(p1);
                pl[1] = to_tf32(p1 - __uint_as_float(ph[1]));
                mma_tf32(o[nt], vh, ph);
                mma_tf32(o[nt], vh, pl);
                mma_tf32(o[nt], vl, ph);
            }
        }
        // ---- epilogue: *inv, out-BN, stage ----
        float sc0 = osc[row], sh0 = osh[row];
        float sc1 = osc[row + 8], sh1 = osh[row + 8];
#pragma unroll
        for (int nt = 0; nt < 2; nt++) {
            int i = i0 + nt * 8 + 2 * kq;
            float iv0 = sinv[i], iv1 = sinv[i + 1];
            ostage[(row * 128 + i) * 4 + ww]           = o[nt][0] * iv0 * sc0 + sh0;
            ostage[(row * 128 + i + 1) * 4 + ww]       = o[nt][1] * iv1 * sc0 + sh0;
            ostage[((row + 8) * 128 + i) * 4 + ww]     = o[nt][2] * iv0 * sc1 + sh1;
            ostage[((row + 8) * 128 + i + 1) * 4 + ww] = o[nt][3] * iv1 * sc1 + sh1;
        }
        __syncthreads();
    }
    // cooperative write-out: 4 contiguous w per (c, h)
    float* dst = out + (size_t)(n * 128 + g * 16) * 16384 + w0;
#pragma unroll
    for (int k = 0; k < 8; k++) {
        int f = tid + k * 256;
        int c = f >> 7, h = f & 127;
        float4 a = *(float4*)&ostage[(c * 128 + h) * 4];
        *(float4*)(dst + (size_t)c * 16384 + h * 128) = a;
    }
}

extern "C" void kernel_launch(void* const* d_in, const int* in_sizes, int n_in,
                              void* d_out, int out_size) {
    const float* x    = (const float*)d_in[0];
    const float* wq   = (const float*)d_in[1];
    const float* qg   = (const float*)d_in[2];
    const float* qb   = (const float*)d_in[3];
    const float* qm   = (const float*)d_in[4];
    const float* qv   = (const float*)d_in[5];
    const float* simg = (const float*)d_in[6];
    // d_in[7] sim_beta, d_in[8] sim_mean: shift cancels in softmax
    const float* simv = (const float*)d_in[9];
    const float* og   = (const float*)d_in[10];
    const float* obt  = (const float*)d_in[11];
    const float* om   = (const float*)d_in[12];
    const float* ov   = (const float*)d_in[13];
    float* out = (float*)d_out;

    cudaFuncSetAttribute(qkv_kernel,
                         cudaFuncAttributeMaxDynamicSharedMemorySize, QSM);
    cudaFuncSetAttribute(attn_kernel,
                         cudaFuncAttributeMaxDynamicSharedMemorySize, SMEM2);

    wt_kernel<<<128, 256>>>(wq);
    qkv_kernel<<<dim3(128, 4, 8), 128, QSM>>>(x, qg, qb, qm, qv);
    attn_kernel<<<dim3(32, 8, 8), 256, SMEM2>>>(simg, simv, og, obt, om, ov, out);
}

// round 8
// speedup vs baseline: 1.1590x; 1.1590x over previous
#include <cuda_runtime.h>

#define EPS 1e-5f

typedef unsigned long long u64;
typedef unsigned int u32;

union f2u { u64 u; float2 f; };

__device__ __forceinline__ u64 pack2(float lo, float hi) {
    u64 r; asm("mov.b64 %0, {%1,%2};" : "=l"(r) : "f"(lo), "f"(hi)); return r;
}
__device__ __forceinline__ void ffma2(u64 &d, u64 a, u64 b) {
    asm("fma.rn.f32x2 %0, %1, %2, %0;" : "+l"(d) : "l"(a), "l"(b));
}
__device__ __forceinline__ u32 to_tf32(float v) {
    u32 r; asm("cvt.rna.tf32.f32 %0, %1;" : "=r"(r) : "f"(v)); return r;
}
__device__ __forceinline__ void mma_tf32(float* d, const u32* a, const u32* b) {
    asm volatile(
        "mma.sync.aligned.m16n8k8.row.col.f32.tf32.tf32.f32 "
        "{%0,%1,%2,%3}, {%4,%5,%6,%7}, {%8,%9}, {%0,%1,%2,%3};\n"
        : "+f"(d[0]), "+f"(d[1]), "+f"(d[2]), "+f"(d[3])
        : "r"(a[0]), "r"(a[1]), "r"(a[2]), "r"(a[3]), "r"(b[0]), "r"(b[1]));
}

// Scratch: qkv[n=8][o=256][h=128][w=128] fp32 = 128 MB
__device__ float g_qkv[33554432];
// W transposed+split: [c=128][o=256] hi / lo
__device__ float g_wt_hi[32768];
__device__ float g_wt_lo[32768];

// ---------------- Kernel 0: transpose + tf32-split W ----------------
__global__ void wt_kernel(const float* __restrict__ w) {
    int idx = blockIdx.x * 256 + threadIdx.x;
    int o = idx >> 7, c = idx & 127;
    float v = w[idx];
    float hf = __uint_as_float(to_tf32(v));
    g_wt_hi[c * 256 + o] = hf;
    g_wt_lo[c * 256 + o] = __uint_as_float(to_tf32(v - hf));
}

// ---------------- Kernel 1: QKV GEMM via tf32 mma.sync + BN (from R4) ----------------
#define QSM (26752 * 4)

__global__ __launch_bounds__(128) void qkv_kernel(
    const float* __restrict__ x,
    const float* __restrict__ qg, const float* __restrict__ qb,
    const float* __restrict__ qm, const float* __restrict__ qv) {
    extern __shared__ float qs[];
    float* xs_hi = qs;
    float* xs_lo = qs + 8704;
    float* ws_hi = qs + 17408;
    float* ws_lo = qs + 22016;
    float* sbn   = qs + 26624;
    float* tbn   = qs + 26688;

    int tid = threadIdx.x;
    int lane = tid & 31, wid = tid >> 5;
    int wm = wid >> 1, wn = wid & 1;
    int pt = blockIdx.x, ot = blockIdx.y, nb = blockIdx.z;
    const float* xp = x + (size_t)nb * (128 * 16384) + pt * 128;

    if (tid < 64) {
        int o = ot * 64 + tid;
        float s = qg[o] * rsqrtf(qv[o] + EPS);
        sbn[tid] = s;
        tbn[tid] = qb[o] - qm[o] * s;
    }

    float d[2][8][4];
#pragma unroll
    for (int m = 0; m < 2; m++)
#pragma unroll
        for (int n = 0; n < 8; n++)
#pragma unroll
            for (int r = 0; r < 4; r++) d[m][n][r] = 0.f;

    int row = lane >> 2, kq = lane & 3;

    for (int cc = 0; cc < 2; cc++) {
#pragma unroll
        for (int k = 0; k < 16; k++) {
            int f = tid + k * 128;
            int c = f >> 5, p4 = (f & 31) << 2;
            float4 v = *(const float4*)(xp + (size_t)(cc * 64 + c) * 16384 + p4);
            float4 h, l;
            h.x = __uint_as_float(to_tf32(v.x)); l.x = __uint_as_float(to_tf32(v.x - h.x));
            h.y = __uint_as_float(to_tf32(v.y)); l.y = __uint_as_float(to_tf32(v.y - h.y));
            h.z = __uint_as_float(to_tf32(v.z)); l.z = __uint_as_float(to_tf32(v.z - h.z));
            h.w = __uint_as_float(to_tf32(v.w)); l.w = __uint_as_float(to_tf32(v.w - h.w));
            *(float4*)&xs_hi[c * 136 + p4] = h;
            *(float4*)&xs_lo[c * 136 + p4] = l;
        }
#pragma unroll
        for (int k = 0; k < 8; k++) {
            int f = tid + k * 128;
            int c = f >> 4, o4 = (f & 15) << 2;
            *(float4*)&ws_hi[c * 72 + o4] =
                *(const float4*)(g_wt_hi + (cc * 64 + c) * 256 + ot * 64 + o4);
            *(float4*)&ws_lo[c * 72 + o4] =
                *(const float4*)(g_wt_lo + (cc * 64 + c) * 256 + ot * 64 + o4);
        }
        __syncthreads();

#pragma unroll
        for (int kc = 0; kc < 8; kc++) {
            int k0 = kc * 8 + kq;
            u32 ah[2][4], al[2][4];
#pragma unroll
            for (int m = 0; m < 2; m++) {
                int wo = wm * 32 + m * 16;
                ah[m][0] = __float_as_uint(ws_hi[k0 * 72 + wo + row]);
                ah[m][1] = __float_as_uint(ws_hi[k0 * 72 + wo + row + 8]);
                ah[m][2] = __float_as_uint(ws_hi[(k0 + 4) * 72 + wo + row]);
                ah[m][3] = __float_as_uint(ws_hi[(k0 + 4) * 72 + wo + row + 8]);
                al[m][0] = __float_as_uint(ws_lo[k0 * 72 + wo + row]);
                al[m][1] = __float_as_uint(ws_lo[k0 * 72 + wo + row + 8]);
                al[m][2] = __float_as_uint(ws_lo[(k0 + 4) * 72 + wo + row]);
                al[m][3] = __float_as_uint(ws_lo[(k0 + 4) * 72 + wo + row + 8]);
            }
#pragma unroll
            for (int n = 0; n < 8; n++) {
                int pc = wn * 64 + n * 8 + row;
                u32 bh[2], bl[2];
                bh[0] = __float_as_uint(xs_hi[k0 * 136 + pc]);
                bh[1] = __float_as_uint(xs_hi[(k0 + 4) * 136 + pc]);
                bl[0] = __float_as_uint(xs_lo[k0 * 136 + pc]);
                bl[1] = __float_as_uint(xs_lo[(k0 + 4) * 136 + pc]);
#pragma unroll
                for (int m = 0; m < 2; m++) {
                    mma_tf32(d[m][n], ah[m], bh);
                    mma_tf32(d[m][n], ah[m], bl);
                    mma_tf32(d[m][n], al[m], bh);
                }
            }
        }
        __syncthreads();
    }
#pragma unroll
    for (int m = 0; m < 2; m++) {
        int lo0 = wm * 32 + m * 16 + row;
        float s0 = sbn[lo0],     t0 = tbn[lo0];
        float s1 = sbn[lo0 + 8], t1 = tbn[lo0 + 8];
        int o0 = ot * 64 + lo0;
#pragma unroll
        for (int n = 0; n < 8; n++) {
            int p = pt * 128 + wn * 64 + n * 8 + kq * 2;
            float2 r0, r1;
            r0.x = d[m][n][0] * s0 + t0; r0.y = d[m][n][1] * s0 + t0;
            r1.x = d[m][n][2] * s1 + t1; r1.y = d[m][n][3] * s1 + t1;
            *(float2*)(g_qkv + (size_t)(nb * 256 + o0) * 16384 + p) = r0;
            *(float2*)(g_qkv + (size_t)(nb * 256 + o0 + 8) * 16384 + p) = r1;
        }
    }
}

// ---------------- Kernel 2: scalar attention, 4 rows/thread ----------------
// 256 threads = 8 j-groups (16 j each) x 32 lanes; lane i owns rows i+32r.
// smem (floats):
//   stage [4][32][128] : 0      (16384)
//   obuf  [8][16][128] : 16384  (16384)
//   redm  [8][128]     : 32768  (1024)
//   reds  [8][128]     : 33792  (1024)
//   sinv  [128]        : 34816  (128)
//   ostage[16][128][4] : 34944  (8192)
//   osc[16], osh[16]   : 43136
#define SMEM2 (43168 * 4)

__global__ __launch_bounds__(256) void attn_kernel(
    const float* __restrict__ simg, const float* __restrict__ simv,
    const float* __restrict__ og, const float* __restrict__ obt,
    const float* __restrict__ om, const float* __restrict__ ov,
    float* __restrict__ out) {
    extern __shared__ float sm[];
    float* stage  = sm;
    float* obuf   = sm + 16384;
    float* redm   = sm + 32768;
    float* reds   = sm + 33792;
    float* sinv   = sm + 34816;
    float* ostage = sm + 34944;
    float* osc    = sm + 43136;
    float* osh    = sm + 43152;

    int tid = threadIdx.x;
    int w0 = blockIdx.x * 4;
    int head = blockIdx.y;
    int n  = blockIdx.z;

    // stage 32ch x 128h x 4w (coalesced float4 over w)
    const float* src = g_qkv + (size_t)(n * 256 + head * 32) * 16384 + w0;
#pragma unroll
    for (int k = 0; k < 16; k++) {
        int f = tid + k * 256;
        int h = f & 127, ch = f >> 7;
        float4 v4 = *(const float4*)(src + (size_t)ch * 16384 + h * 128);
        stage[(0 * 32 + ch) * 128 + h] = v4.x;
        stage[(1 * 32 + ch) * 128 + h] = v4.y;
        stage[(2 * 32 + ch) * 128 + h] = v4.z;
        stage[(3 * 32 + ch) * 128 + h] = v4.w;
    }
    if (tid < 16) {
        int co = head * 16 + tid;
        float s = og[co] * rsqrtf(ov[co] + EPS);
        osc[tid] = s;
        osh[tid] = obt[co] - om[co] * s;
    }
    // sim BN shift cancels in softmax; positive scale folded into q.
    float simscale = simg[head] * rsqrtf(simv[head] + EPS);
    __syncthreads();

    int jg = tid >> 5;       // j-group (= warp id)
    int i  = tid & 31;       // row base; rows i + 32r
    int j0 = jg * 16;

#pragma unroll 1
    for (int ww = 0; ww < 4; ww++) {
        const float* Q = stage + ww * 4096;
        // q rows, pre-scaled, duplicated for f32x2
        u64 qd[4][8];
#pragma unroll
        for (int r = 0; r < 4; r++)
#pragma unroll
            for (int c = 0; c < 8; c++) {
                float v = Q[c * 128 + i + 32 * r] * simscale;
                qd[r][c] = pack2(v, v);
            }
        // S[4 rows][16 j] as 8 f2u per row
        f2u s2[4][8];
#pragma unroll
        for (int r = 0; r < 4; r++)
#pragma unroll
            for (int k = 0; k < 8; k++) s2[r][k].u = 0ull;
#pragma unroll
        for (int jj = 0; jj < 16; jj += 4) {
#pragma unroll
            for (int c = 0; c < 8; c++) {
                float4 k4 = *(const float4*)(Q + (8 + c) * 128 + j0 + jj);
                u64 kb0 = pack2(k4.x, k4.y);
                u64 kb1 = pack2(k4.z, k4.w);
#pragma unroll
                for (int r = 0; r < 4; r++) {
                    ffma2(s2[r][jj / 2].u,     qd[r][c], kb0);
                    ffma2(s2[r][jj / 2 + 1].u, qd[r][c], kb1);
                }
            }
        }
        // row-max partials
#pragma unroll
        for (int r = 0; r < 4; r++) {
            float m = -1e30f;
#pragma unroll
            for (int k = 0; k < 8; k++)
                m = fmaxf(m, fmaxf(s2[r][k].f.x, s2[r][k].f.y));
            redm[jg * 128 + i + 32 * r] = m;
        }
        __syncthreads();
        // full max, exp, sum partials
#pragma unroll
        for (int r = 0; r < 4; r++) {
            int row = i + 32 * r;
            float m = redm[row];
#pragma unroll
            for (int t = 1; t < 8; t++) m = fmaxf(m, redm[t * 128 + row]);
            float sum = 0.f;
#pragma unroll
            for (int k = 0; k < 8; k++) {
                float e0 = __expf(s2[r][k].f.x - m);
                float e1 = __expf(s2[r][k].f.y - m);
                s2[r][k].f.x = e0; s2[r][k].f.y = e1;
                sum += e0 + e1;
            }
            reds[jg * 128 + row] = sum;
        }
        __syncthreads();
        if (jg == 0) {
#pragma unroll
            for (int r = 0; r < 4; r++) {
                int row = i + 32 * r;
                float s = reds[row];
#pragma unroll
                for (int t = 1; t < 8; t++) s += reds[t * 128 + row];
                sinv[row] = 1.f / s;
            }
        }
        // GEMM2: O[c][row] partials over this group's 16 j, two 8-c passes
#pragma unroll
        for (int pass = 0; pass < 2; pass++) {
            f2u oc[8][4];
#pragma unroll
            for (int c = 0; c < 8; c++)
#pragma unroll
                for (int r = 0; r < 4; r++) oc[c][r].u = 0ull;
#pragma unroll
            for (int jj = 0; jj < 16; jj += 4) {
#pragma unroll
                for (int c = 0; c < 8; c++) {
                    float4 v4 = *(const float4*)(Q + (16 + pass * 8 + c) * 128 + j0 + jj);
                    u64 vb0 = pack2(v4.x, v4.y);
                    u64 vb1 = pack2(v4.z, v4.w);
#pragma unroll
                    for (int r = 0; r < 4; r++) {
                        ffma2(oc[c][r].u, s2[r][jj / 2].u,     vb0);
                        ffma2(oc[c][r].u, s2[r][jj / 2 + 1].u, vb1);
                    }
                }
            }
#pragma unroll
            for (int c = 0; c < 8; c++)
#pragma unroll
                for (int r = 0; r < 4; r++)
                    obuf[(jg * 16 + pass * 8 + c) * 128 + i + 32 * r] =
                        oc[c][r].f.x + oc[c][r].f.y;
        }
        __syncthreads();
        // reduce partials + out-BN + stage
#pragma unroll
        for (int k = 0; k < 8; k++) {
            int f = tid + k * 256;
            int c = f >> 7, row = f & 127;
            float s = obuf[c * 128 + row];
#pragma unroll
            for (int t = 1; t < 8; t++) s += obuf[(t * 16 + c) * 128 + row];
            ostage[(c * 128 + row) * 4 + ww] = s * sinv[row] * osc[c] + osh[c];
        }
        __syncthreads();
    }
    // cooperative write-out: 4 contiguous w per (c, h)
    float* dst = out + (size_t)(n * 128 + head * 16) * 16384 + w0;
#pragma unroll
    for (int k = 0; k < 8; k++) {
        int f = tid + k * 256;
        int c = f >> 7, h = f & 127;
        float4 a = *(float4*)&ostage[(c * 128 + h) * 4];
        *(float4*)(dst + (size_t)c * 16384 + h * 128) = a;
    }
}

extern "C" void kernel_launch(void* const* d_in, const int* in_sizes, int n_in,
                              void* d_out, int out_size) {
    const float* x    = (const float*)d_in[0];
    const float* wq   = (const float*)d_in[1];
    const float* qg   = (const float*)d_in[2];
    const float* qb   = (const float*)d_in[3];
    const float* qm   = (const float*)d_in[4];
    const float* qv   = (const float*)d_in[5];
    const float* simg = (const float*)d_in[6];
    // d_in[7] sim_beta, d_in[8] sim_mean: shift cancels in softmax
    const float* simv = (const float*)d_in[9];
    const float* og   = (const float*)d_in[10];
    const float* obt  = (const float*)d_in[11];
    const float* om   = (const float*)d_in[12];
    const float* ov   = (const float*)d_in[13];
    float* out = (float*)d_out;

    cudaFuncSetAttribute(qkv_kernel,
                         cudaFuncAttributeMaxDynamicSharedMemorySize, QSM);
    cudaFuncSetAttribute(attn_kernel,
                         cudaFuncAttributeMaxDynamicSharedMemorySize, SMEM2);

    wt_kernel<<<128, 256>>>(wq);
    qkv_kernel<<<dim3(128, 4, 8), 128, QSM>>>(x, qg, qb, qm, qv);
    attn_kernel<<<dim3(32, 8, 8), 256, SMEM2>>>(simg, simv, og, obt, om, ov, out);
}